// round 16
// baseline (speedup 1.0000x reference)
#include <cuda_runtime.h>
#include <cstdint>

#define NH      16
#define NSPLIT  28            // 28*16 = 448 CTAs ~ one wave at occ 3 on 152 SMs
#define CHUNK   586           // ceil(16384/28)
#define KS      32            // samples per panel
#define NSAMP   16384
#define DECAYF  0.95f

// Deterministic split-K partials: [split][h][64][64] ~7.3MB
__device__ float g_partial[NSPLIT * NH * 4096];

__device__ __forceinline__ uint32_t smem_u32(const void* p) {
    uint32_t a;
    asm("{ .reg .u64 t; cvta.to.shared.u64 t, %1; cvt.u32.u64 %0, t; }"
        : "=r"(a) : "l"(p));
    return a;
}

#define LDSM_X4_T(r, addr)                                                     \
    asm volatile("ldmatrix.sync.aligned.m8n8.x4.trans.shared.b16 "             \
                 "{%0,%1,%2,%3}, [%4];"                                        \
                 : "=r"((r)[0]), "=r"((r)[1]), "=r"((r)[2]), "=r"((r)[3])      \
                 : "r"(addr))

__device__ __forceinline__ void mma16816(float* c, const uint32_t* a,
                                         uint32_t b0, uint32_t b1)
{
    asm volatile(
        "mma.sync.aligned.m16n8k16.row.col.f32.f16.f16.f32 "
        "{%0,%1,%2,%3}, {%4,%5,%6,%7}, {%8,%9}, {%0,%1,%2,%3};"
        : "+f"(c[0]), "+f"(c[1]), "+f"(c[2]), "+f"(c[3])
        : "r"(a[0]), "r"(a[1]), "r"(a[2]), "r"(a[3]), "r"(b0), "r"(b1));
}

// smem tile map (per CTA, single buffer, 8 KB):
//   KSH @ 0 (rho*k, fp16), VSH @ 4096 (v, fp16)
// tile = [32 s][64 dim] fp16, 128B/row, XOR swizzle: off ^ ((s&7)<<4)

__global__ __launch_bounds__(256, 3)
void l1writer_mma_kernel(const float* __restrict__ keys,
                         const float* __restrict__ values,
                         const float* __restrict__ rho)
{
    __shared__ __align__(128) char buf[8192];
    const int tid  = threadIdx.x, lane = tid & 31, wid = tid >> 5;
    const int split = blockIdx.x, h = blockIdx.y;
    const int n0   = split * CHUNK;
    const int nend = min(n0 + CHUNK, NSAMP);
    const int npanel = (nend - n0 + KS - 1) / KS;
    const uint32_t sb = smem_u32(buf);

    // Warp tile: 4 warps along M (dk), 2 along N (dv); each warp 16x32
    const int m0  = (wid >> 1) * 16;
    const int nn0 = (wid & 1) * 32;

    // Per-lane LDSM addresses (logical -> swizzled), k16-step advance = +2048B
    const int half = lane >> 3, l7 = lane & 7;
    const int a_s = l7 + ((half >> 1) << 3);
    const int a_m = m0 + ((half & 1) << 3);
    const uint32_t aoff = (uint32_t)(a_s * 128 + a_m * 2) ^ ((a_s & 7) << 4);
    const int b_s = l7 + ((half & 1) << 3);
    const int b_n = nn0 + ((half >> 1) << 3);
    const uint32_t boff0 = (uint32_t)(b_s * 128 + b_n * 2) ^ ((b_s & 7) << 4);
    const uint32_t boff1 = (uint32_t)(b_s * 128 + (b_n + 16) * 2) ^ ((b_s & 7) << 4);

    const uint32_t aAh  = sb + aoff;
    const uint32_t aBh0 = sb + 4096 + boff0;
    const uint32_t aBh1 = sb + 4096 + boff1;

    float c[4][4];
#pragma unroll
    for (int t = 0; t < 4; ++t)
#pragma unroll
        for (int i = 0; i < 4; ++i) c[t][i] = 0.f;

    // Loader: 1024 float4 per panel (512 K + 512 V); 4 per thread
    float4 kv[4];
    float  rr[2];

#pragma unroll
    for (int j = 0; j < 4; ++j) {               // prefetch panel 0
        int idx = tid + j * 256;
        int s   = (idx & 511) >> 4;
        int l4  = idx & 15;
        int n   = n0 + s;
        if (n < nend) {
            const float* src = ((j < 2) ? keys : values)
                             + (size_t)n * (NH * 64) + h * 64 + l4 * 4;
            kv[j] = *(const float4*)src;
            if (j < 2) rr[j] = __ldg(rho + n);
        } else {
            kv[j] = make_float4(0.f, 0.f, 0.f, 0.f);
            if (j < 2) rr[j] = 0.f;
        }
    }

    for (int p = 0; p < npanel; ++p) {
        __syncthreads();   // previous panel's compute done before overwrite
        // Commit prefetched regs -> smem (fp16 convert; K scaled by rho)
#pragma unroll
        for (int j = 0; j < 4; ++j) {
            int idx = tid + j * 256;
            int s   = (idx & 511) >> 4;
            int l4  = idx & 15;
            float r = (j < 2) ? rr[j] : 1.f;
            float4 f = kv[j];
            float x0 = f.x * r, x1 = f.y * r, x2 = f.z * r, x3 = f.w * r;
            uint32_t h01, h23;
            asm("cvt.rn.f16x2.f32 %0, %1, %2;" : "=r"(h01) : "f"(x1), "f"(x0));
            asm("cvt.rn.f16x2.f32 %0, %1, %2;" : "=r"(h23) : "f"(x3), "f"(x2));
            uint32_t off = (uint32_t)(s * 128 + l4 * 8) ^ ((s & 7) << 4);
            char* hp = buf + ((j < 2) ? 0 : 4096) + off;
            *(uint2*)hp = make_uint2(h01, h23);
        }
        __syncthreads();

        // Prefetch next panel (hidden under LDSM+HMMA below)
        if (p + 1 < npanel) {
#pragma unroll
            for (int j = 0; j < 4; ++j) {
                int idx = tid + j * 256;
                int s   = (idx & 511) >> 4;
                int l4  = idx & 15;
                int n   = n0 + (p + 1) * KS + s;
                if (n < nend) {
                    const float* src = ((j < 2) ? keys : values)
                                     + (size_t)n * (NH * 64) + h * 64 + l4 * 4;
                    kv[j] = *(const float4*)src;
                    if (j < 2) rr[j] = __ldg(rho + n);
                } else {
                    kv[j] = make_float4(0.f, 0.f, 0.f, 0.f);
                    if (j < 2) rr[j] = 0.f;
                }
            }
        }

        // Compute: 2 k16-steps, 3 LDSM.x4 + 4 HMMA each
#pragma unroll
        for (int st = 0; st < 2; ++st) {
            const uint32_t adv = st * 2048;
            uint32_t ah[4], bh[4], bh2[4];
            LDSM_X4_T(ah,  aAh  + adv);
            LDSM_X4_T(bh,  aBh0 + adv);
            LDSM_X4_T(bh2, aBh1 + adv);
            mma16816(c[0], ah, bh[0],  bh[1]);
            mma16816(c[1], ah, bh[2],  bh[3]);
            mma16816(c[2], ah, bh2[0], bh2[1]);
            mma16816(c[3], ah, bh2[2], bh2[3]);
        }
    }

    // Write deterministic partial tile
    const int gid = lane >> 2, tig = lane & 3;
    float* base = g_partial + ((size_t)split * NH + h) * 4096;
#pragma unroll
    for (int t = 0; t < 4; ++t) {
        int nc = nn0 + t * 8 + 2 * tig;
        *(float2*)(base + (m0 + gid)     * 64 + nc) = make_float2(c[t][0], c[t][1]);
        *(float2*)(base + (m0 + gid + 8) * 64 + nc) = make_float2(c[t][2], c[t][3]);
    }
}

// out[i] = 0.95*memory[i] + sum_s partial[s][i]
__global__ __launch_bounds__(256)
void l1writer_reduce_kernel(const float* __restrict__ memory,
                            float* __restrict__ out)
{
    int i = blockIdx.x * 256 + threadIdx.x;   // 0..65535
    float acc = DECAYF * memory[i];
#pragma unroll
    for (int s = 0; s < NSPLIT; ++s)
        acc += g_partial[(size_t)s * (NH * 4096) + i];
    out[i] = acc;
}

extern "C" void kernel_launch(void* const* d_in, const int* in_sizes, int n_in,
                              void* d_out, int out_size)
{
    const float* memory = (const float*)d_in[0];  // (16,64,64)
    const float* keys   = (const float*)d_in[1];  // (4,4096,16,64)
    const float* values = (const float*)d_in[2];  // (4,4096,16,64)
    const float* rho    = (const float*)d_in[3];  // (4,4096)
    float* out = (float*)d_out;

    dim3 grid(NSPLIT, NH);
    l1writer_mma_kernel<<<grid, 256>>>(keys, values, rho);
    l1writer_reduce_kernel<<<(NH * 4096) / 256, 256>>>(memory, out);
}

// round 17
// speedup vs baseline: 1.1967x; 1.1967x over previous
#include <cuda_runtime.h>
#include <cstdint>

#define NH      16
#define NSPLIT  28            // 28*16 = 448 CTAs ~ one wave at occ 3 on 152 SMs
#define CHUNK   586           // ceil(16384/28)
#define KS      32            // samples per panel
#define NSAMP   16384
#define DECAYF  0.95f

// Deterministic split-K partials: [split][h][64][64] ~7.3MB
__device__ float g_partial[NSPLIT * NH * 4096];

__device__ __forceinline__ uint32_t smem_u32(const void* p) {
    uint32_t a;
    asm("{ .reg .u64 t; cvta.to.shared.u64 t, %1; cvt.u32.u64 %0, t; }"
        : "=r"(a) : "l"(p));
    return a;
}

#define LDSM_X4_T(r, addr)                                                     \
    asm volatile("ldmatrix.sync.aligned.m8n8.x4.trans.shared.b16 "             \
                 "{%0,%1,%2,%3}, [%4];"                                        \
                 : "=r"((r)[0]), "=r"((r)[1]), "=r"((r)[2]), "=r"((r)[3])      \
                 : "r"(addr))

__device__ __forceinline__ void mma16816(float* c, const uint32_t* a,
                                         uint32_t b0, uint32_t b1)
{
    asm volatile(
        "mma.sync.aligned.m16n8k16.row.col.f32.f16.f16.f32 "
        "{%0,%1,%2,%3}, {%4,%5,%6,%7}, {%8,%9}, {%0,%1,%2,%3};"
        : "+f"(c[0]), "+f"(c[1]), "+f"(c[2]), "+f"(c[3])
        : "r"(a[0]), "r"(a[1]), "r"(a[2]), "r"(a[3]), "r"(b0), "r"(b1));
}

// smem tile map (per CTA, single buffer, 8 KB):
//   KSH @ 0 (rho*k, fp16), VSH @ 4096 (v, fp16)
// tile = [32 s][64 dim] fp16, 128B/row, XOR swizzle: off ^ ((s&7)<<4)

__global__ __launch_bounds__(256, 3)
void l1writer_mma_kernel(const float* __restrict__ keys,
                         const float* __restrict__ values,
                         const float* __restrict__ rho)
{
    __shared__ __align__(128) char buf[8192];
    const int tid  = threadIdx.x, lane = tid & 31, wid = tid >> 5;
    const int split = blockIdx.x, h = blockIdx.y;
    const int n0   = split * CHUNK;
    const int nend = min(n0 + CHUNK, NSAMP);
    const int npanel = (nend - n0 + KS - 1) / KS;
    const uint32_t sb = smem_u32(buf);

    // Warp tile: 4 warps along M (dk), 2 along N (dv); each warp 16x32
    const int m0  = (wid >> 1) * 16;
    const int nn0 = (wid & 1) * 32;

    // Per-lane LDSM addresses (logical -> swizzled), k16-step advance = +2048B
    const int half = lane >> 3, l7 = lane & 7;
    const int a_s = l7 + ((half >> 1) << 3);
    const int a_m = m0 + ((half & 1) << 3);
    const uint32_t aoff = (uint32_t)(a_s * 128 + a_m * 2) ^ ((a_s & 7) << 4);
    const int b_s = l7 + ((half & 1) << 3);
    const int b_n = nn0 + ((half >> 1) << 3);
    const uint32_t boff0 = (uint32_t)(b_s * 128 + b_n * 2) ^ ((b_s & 7) << 4);
    const uint32_t boff1 = (uint32_t)(b_s * 128 + (b_n + 16) * 2) ^ ((b_s & 7) << 4);

    const uint32_t aAh  = sb + aoff;
    const uint32_t aBh0 = sb + 4096 + boff0;
    const uint32_t aBh1 = sb + 4096 + boff1;

    float c[4][4];
#pragma unroll
    for (int t = 0; t < 4; ++t)
#pragma unroll
        for (int i = 0; i < 4; ++i) c[t][i] = 0.f;

    // Two loader register sets for 2-panel-deep LDG pipeline
    float4 kvA[4], kvB[4];
    float  rrA[2], rrB[2];

#define LOAD_SET(KV, RR, P)                                                    \
    _Pragma("unroll")                                                          \
    for (int j = 0; j < 4; ++j) {                                              \
        int idx = tid + j * 256;                                               \
        int s   = (idx & 511) >> 4;                                            \
        int l4  = idx & 15;                                                    \
        int n   = n0 + (P) * KS + s;                                           \
        if (n < nend) {                                                        \
            const float* src = ((j < 2) ? keys : values)                       \
                             + (size_t)n * (NH * 64) + h * 64 + l4 * 4;        \
            KV[j] = *(const float4*)src;                                       \
            if (j < 2) RR[j] = __ldg(rho + n);                                 \
        } else {                                                               \
            KV[j] = make_float4(0.f, 0.f, 0.f, 0.f);                           \
            if (j < 2) RR[j] = 0.f;                                            \
        }                                                                      \
    }

#define STORE_SET(KV, RR)                                                      \
    _Pragma("unroll")                                                          \
    for (int j = 0; j < 4; ++j) {                                              \
        int idx = tid + j * 256;                                               \
        int s   = (idx & 511) >> 4;                                            \
        int l4  = idx & 15;                                                    \
        float r = (j < 2) ? RR[j] : 1.f;                                       \
        float4 f = KV[j];                                                      \
        float x0 = f.x * r, x1 = f.y * r, x2 = f.z * r, x3 = f.w * r;          \
        uint32_t h01, h23;                                                     \
        asm("cvt.rn.f16x2.f32 %0, %1, %2;" : "=r"(h01) : "f"(x1), "f"(x0));    \
        asm("cvt.rn.f16x2.f32 %0, %1, %2;" : "=r"(h23) : "f"(x3), "f"(x2));    \
        uint32_t off = (uint32_t)(s * 128 + l4 * 8) ^ ((s & 7) << 4);          \
        char* hp = buf + ((j < 2) ? 0 : 4096) + off;                           \
        *(uint2*)hp = make_uint2(h01, h23);                                    \
    }

#define COMPUTE_PANEL()                                                        \
    _Pragma("unroll")                                                          \
    for (int st = 0; st < 2; ++st) {                                           \
        const uint32_t adv = st * 2048;                                        \
        uint32_t ah[4], bh[4], bh2[4];                                         \
        LDSM_X4_T(ah,  aAh  + adv);                                            \
        LDSM_X4_T(bh,  aBh0 + adv);                                            \
        LDSM_X4_T(bh2, aBh1 + adv);                                            \
        mma16816(c[0], ah, bh[0],  bh[1]);                                     \
        mma16816(c[1], ah, bh[2],  bh[3]);                                     \
        mma16816(c[2], ah, bh2[0], bh2[1]);                                    \
        mma16816(c[3], ah, bh2[2], bh2[3]);                                    \
    }

    // Prologue: panels 0 and 1 in flight
    LOAD_SET(kvA, rrA, 0);
    LOAD_SET(kvB, rrB, 1);

    for (int p = 0; p < npanel; p += 2) {
        // Panel p (set A)
        __syncthreads();
        STORE_SET(kvA, rrA);
        __syncthreads();
        LOAD_SET(kvA, rrA, p + 2);       // 2 panels ahead; predicated to zeros past end
        COMPUTE_PANEL();

        // Panel p+1 (set B)
        if (p + 1 < npanel) {
            __syncthreads();
            STORE_SET(kvB, rrB);
            __syncthreads();
            LOAD_SET(kvB, rrB, p + 3);
            COMPUTE_PANEL();
        }
    }

    // Write deterministic partial tile
    const int gid = lane >> 2, tig = lane & 3;
    float* base = g_partial + ((size_t)split * NH + h) * 4096;
#pragma unroll
    for (int t = 0; t < 4; ++t) {
        int nc = nn0 + t * 8 + 2 * tig;
        *(float2*)(base + (m0 + gid)     * 64 + nc) = make_float2(c[t][0], c[t][1]);
        *(float2*)(base + (m0 + gid + 8) * 64 + nc) = make_float2(c[t][2], c[t][3]);
    }
}

// out[i] = 0.95*memory[i] + sum_s partial[s][i]
__global__ __launch_bounds__(256)
void l1writer_reduce_kernel(const float* __restrict__ memory,
                            float* __restrict__ out)
{
    int i = blockIdx.x * 256 + threadIdx.x;   // 0..65535
    float acc = DECAYF * memory[i];
#pragma unroll
    for (int s = 0; s < NSPLIT; ++s)
        acc += g_partial[(size_t)s * (NH * 4096) + i];
    out[i] = acc;
}

extern "C" void kernel_launch(void* const* d_in, const int* in_sizes, int n_in,
                              void* d_out, int out_size)
{
    const float* memory = (const float*)d_in[0];  // (16,64,64)
    const float* keys   = (const float*)d_in[1];  // (4,4096,16,64)
    const float* values = (const float*)d_in[2];  // (4,4096,16,64)
    const float* rho    = (const float*)d_in[3];  // (4,4096)
    float* out = (float*)d_out;

    dim3 grid(NSPLIT, NH);
    l1writer_mma_kernel<<<grid, 256>>>(keys, values, rho);
    l1writer_reduce_kernel<<<(NH * 4096) / 256, 256>>>(memory, out);
}